// round 11
// baseline (speedup 1.0000x reference)
#include <cuda_runtime.h>
#include <cuda_bf16.h>
#include <cstdint>

#define B_TOTAL  131072
#define DIM      1024
#define NH       21
#define THREADS  128
#define WROWS    32                  // rows per warp (2 m16 tiles)
#define BROWS    128                 // rows per block (4 warps)
#define NKS      (DIM / 16)          // 64 k16 steps
#define NT       3                   // n-tiles of 8 (21 -> 24)
#define PFD      8                   // L2 prefetch distance (k-steps)

// W fragments, k-permuted to match float4 lane loads.
// uint4 = {b0_hi, b1_hi, b0_lo, b1_lo}
__device__ uint4 g_wf[NKS][NT][32];

__global__ void prep_wfrag(const float* __restrict__ W)
{
    int idx = blockIdx.x * blockDim.x + threadIdx.x;
    if (idx >= NKS * NT * 32) return;
    int l  = idx & 31;
    int nt = (idx >> 5) % NT;
    int ks = idx / (NT * 32);
    int n  = nt * 8 + (l >> 2);
    int col = ks * 16 + 4 * (l & 3);
    float4 wv = make_float4(0.f, 0.f, 0.f, 0.f);
    if (n < NH) wv = *(const float4*)&W[(long long)n * DIM + col];
    uint32_t h0, h1, q0, q1;
    asm("cvt.rn.bf16x2.f32 %0, %1, %2;" : "=r"(h0) : "f"(wv.y), "f"(wv.x));
    asm("cvt.rn.bf16x2.f32 %0, %1, %2;" : "=r"(h1) : "f"(wv.w), "f"(wv.z));
    float rx = wv.x - __uint_as_float(h0 << 16);
    float ry = wv.y - __uint_as_float(h0 & 0xffff0000u);
    float rz = wv.z - __uint_as_float(h1 << 16);
    float rw = wv.w - __uint_as_float(h1 & 0xffff0000u);
    asm("cvt.rn.bf16x2.f32 %0, %1, %2;" : "=r"(q0) : "f"(ry), "f"(rx));
    asm("cvt.rn.bf16x2.f32 %0, %1, %2;" : "=r"(q1) : "f"(rw), "f"(rz));
    g_wf[ks][nt][l] = make_uint4(h0, h1, q0, q1);
}

#define MMA(c, a0, a1, a2, a3, b0, b1)                                          \
    asm("mma.sync.aligned.m16n8k16.row.col.f32.bf16.bf16.f32 "                  \
        "{%0,%1,%2,%3}, {%4,%5,%6,%7}, {%8,%9}, {%0,%1,%2,%3};"                 \
        : "+f"(c[0]), "+f"(c[1]), "+f"(c[2]), "+f"(c[3])                        \
        : "r"(a0), "r"(a1), "r"(a2), "r"(a3), "r"(b0), "r"(b1))

// float4 (4 consecutive k) -> two packed bf16x2 hi + two residual lo
__device__ __forceinline__ void cvt4(float4 v, uint32_t& h0, uint32_t& h1,
                                     uint32_t& q0, uint32_t& q1)
{
    asm("cvt.rn.bf16x2.f32 %0, %1, %2;" : "=r"(h0) : "f"(v.y), "f"(v.x));
    asm("cvt.rn.bf16x2.f32 %0, %1, %2;" : "=r"(h1) : "f"(v.w), "f"(v.z));
    float rx = v.x - __uint_as_float(h0 << 16);
    float ry = v.y - __uint_as_float(h0 & 0xffff0000u);
    float rz = v.z - __uint_as_float(h1 << 16);
    float rw = v.w - __uint_as_float(h1 & 0xffff0000u);
    asm("cvt.rn.bf16x2.f32 %0, %1, %2;" : "=r"(q0) : "f"(ry), "f"(rx));
    asm("cvt.rn.bf16x2.f32 %0, %1, %2;" : "=r"(q1) : "f"(rw), "f"(rz));
}

__device__ __forceinline__ void pf_l2(const float* p)
{
    asm volatile("prefetch.global.L2 [%0];" :: "l"(p));
}

__global__ __launch_bounds__(THREADS, 4)
void linheads_mma_kernel(const float* __restrict__ x,
                         const float* __restrict__ v_conf,
                         const float* __restrict__ bias,
                         float* __restrict__ result,
                         float* __restrict__ out)
{
    const int t   = threadIdx.x;
    const int wid = t >> 5;
    const int l   = t & 31;

    const long long wb = (long long)blockIdx.x * BROWS + wid * WROWS;
    // frag rows (r, r+8) <-> global rows (2r, 2r+1); lane quad-row r = l>>2
    const float* p00 = x + (wb + 2 * (l >> 2)) * DIM + 4 * (l & 3);

    float c[2][NT][4];
#pragma unroll
    for (int mt = 0; mt < 2; mt++)
#pragma unroll
        for (int nt = 0; nt < NT; nt++)
#pragma unroll
            for (int i = 0; i < 4; i++) c[mt][nt][i] = 0.f;

    // buf[s][mt*2 + rr]: float4 at (row wb + 16mt + 2(l>>2) + rr, 16ks + 4(l&3))
    float4 buf[2][4];
#pragma unroll
    for (int s = 0; s < 2; s++) {
        const int o = s * 16;
        buf[s][0] = __ldcs((const float4*)(p00 + o));
        buf[s][1] = __ldcs((const float4*)(p00 + DIM + o));
        buf[s][2] = __ldcs((const float4*)(p00 + 16 * DIM + o));
        buf[s][3] = __ldcs((const float4*)(p00 + 17 * DIM + o));
    }

#pragma unroll 2
    for (int ks = 0; ks < NKS; ks++) {
        const int p = ks & 1;

        // consume buf[p] into bf16 hi/lo fragments (frees the registers)
        uint32_t ah[2][4], al[2][4];
#pragma unroll
        for (int mt = 0; mt < 2; mt++) {
            cvt4(buf[p][mt * 2 + 0], ah[mt][0], ah[mt][2], al[mt][0], al[mt][2]);
            cvt4(buf[p][mt * 2 + 1], ah[mt][1], ah[mt][3], al[mt][1], al[mt][3]);
        }

        // refill buf[p] with k-step ks+2 (in flight for ~2 iterations)
        if (ks + 2 < NKS) {
            const int o = (ks + 2) * 16;
            buf[p][0] = __ldcs((const float4*)(p00 + o));
            buf[p][1] = __ldcs((const float4*)(p00 + DIM + o));
            buf[p][2] = __ldcs((const float4*)(p00 + 16 * DIM + o));
            buf[p][3] = __ldcs((const float4*)(p00 + 17 * DIM + o));
        }
        // long-range L2 prefetch (~1600 cyc ahead): DRAM -> L2
        if (ks + PFD < NKS) {
            const int o = (ks + PFD) * 16;
            pf_l2(p00 + o);
            pf_l2(p00 + DIM + o);
            pf_l2(p00 + 16 * DIM + o);
            pf_l2(p00 + 17 * DIM + o);
        }

#pragma unroll
        for (int nt = 0; nt < NT; nt++) {
            uint4 wf = g_wf[ks][nt][l];
#pragma unroll
            for (int mt = 0; mt < 2; mt++) {
                MMA(c[mt][nt], ah[mt][0], ah[mt][1], ah[mt][2], ah[mt][3], wf.x, wf.y);
                MMA(c[mt][nt], ah[mt][0], ah[mt][1], ah[mt][2], ah[mt][3], wf.z, wf.w);
                MMA(c[mt][nt], al[mt][0], al[mt][1], al[mt][2], al[mt][3], wf.x, wf.y);
            }
        }
    }

    // ---- epilogue ----
    // c[mt][nt][rr*2+e]: row = wb + 16mt + 2(l>>2) + rr, col = nt*8 + 2(l&3) + e
#pragma unroll
    for (int mt = 0; mt < 2; mt++) {
#pragma unroll
        for (int rr = 0; rr < 2; rr++) {
            const long long row = wb + 16 * mt + 2 * (l >> 2) + rr;
            float res = 0.f;
#pragma unroll
            for (int nt = 0; nt < NT; nt++) {
                int col0 = nt * 8 + 2 * (l & 3);
#pragma unroll
                for (int e = 0; e < 2; e++) {
                    int col = col0 + e;
                    if (col < NH) {
                        float o = c[mt][nt][rr * 2 + e] + bias[col];
                        out[row * NH + col] = o;
                        res += o * v_conf[row * NH + col];
                    }
                }
            }
            res += __shfl_xor_sync(0xffffffffu, res, 1);
            res += __shfl_xor_sync(0xffffffffu, res, 2);
            if ((l & 3) == 0) result[row] = res;
        }
    }
}

extern "C" void kernel_launch(void* const* d_in, const int* in_sizes, int n_in,
                              void* d_out, int out_size)
{
    const float* x      = (const float*)d_in[0];   // [B, DIM]
    const float* v_conf = (const float*)d_in[1];   // [B, NH]
    const float* W      = (const float*)d_in[2];   // [NH, DIM]
    const float* bias   = (const float*)d_in[3];   // [NH]

    float* result = (float*)d_out;                 // [B]
    float* out    = (float*)d_out + B_TOTAL;       // [B, NH]

    prep_wfrag<<<(NKS * NT * 32 + 255) / 256, 256>>>(W);

    dim3 grid(B_TOTAL / BROWS);                    // 1024
    linheads_mma_kernel<<<grid, THREADS>>>(x, v_conf, bias, result, out);
}

// round 12
// speedup vs baseline: 1.0430x; 1.0430x over previous
#include <cuda_runtime.h>
#include <cuda_bf16.h>
#include <cstdint>

#define B_TOTAL  131072
#define DIM      1024
#define NH       21
#define THREADS  128
#define WROWS    32                  // rows per warp (2 m16 tiles)
#define BROWS    128                 // rows per block (4 warps)
#define NKS      (DIM / 16)          // 64 k16 steps
#define NT       3                   // n-tiles of 8 (21 -> 24)
#define STAGES   4

// W fragments, k-permuted to match float4 lane loads.
// uint4 = {b0_hi, b1_hi, b0_lo, b1_lo}
__device__ uint4 g_wf[NKS][NT][32];

__global__ void prep_wfrag(const float* __restrict__ W)
{
    int idx = blockIdx.x * blockDim.x + threadIdx.x;
    if (idx >= NKS * NT * 32) return;
    int l  = idx & 31;
    int nt = (idx >> 5) % NT;
    int ks = idx / (NT * 32);
    int n  = nt * 8 + (l >> 2);
    int col = ks * 16 + 4 * (l & 3);
    float4 wv = make_float4(0.f, 0.f, 0.f, 0.f);
    if (n < NH) wv = *(const float4*)&W[(long long)n * DIM + col];
    uint32_t h0, h1, q0, q1;
    asm("cvt.rn.bf16x2.f32 %0, %1, %2;" : "=r"(h0) : "f"(wv.y), "f"(wv.x));
    asm("cvt.rn.bf16x2.f32 %0, %1, %2;" : "=r"(h1) : "f"(wv.w), "f"(wv.z));
    float rx = wv.x - __uint_as_float(h0 << 16);
    float ry = wv.y - __uint_as_float(h0 & 0xffff0000u);
    float rz = wv.z - __uint_as_float(h1 << 16);
    float rw = wv.w - __uint_as_float(h1 & 0xffff0000u);
    asm("cvt.rn.bf16x2.f32 %0, %1, %2;" : "=r"(q0) : "f"(ry), "f"(rx));
    asm("cvt.rn.bf16x2.f32 %0, %1, %2;" : "=r"(q1) : "f"(rw), "f"(rz));
    g_wf[ks][nt][l] = make_uint4(h0, h1, q0, q1);
}

#define MMA(c, a0, a1, a2, a3, b0, b1)                                          \
    asm("mma.sync.aligned.m16n8k16.row.col.f32.bf16.bf16.f32 "                  \
        "{%0,%1,%2,%3}, {%4,%5,%6,%7}, {%8,%9}, {%0,%1,%2,%3};"                 \
        : "+f"(c[0]), "+f"(c[1]), "+f"(c[2]), "+f"(c[3])                        \
        : "r"(a0), "r"(a1), "r"(a2), "r"(a3), "r"(b0), "r"(b1))

// float4 (4 consecutive k) -> two packed bf16x2 hi + two residual lo
__device__ __forceinline__ void cvt4(float4 v, uint32_t& h0, uint32_t& h1,
                                     uint32_t& q0, uint32_t& q1)
{
    asm("cvt.rn.bf16x2.f32 %0, %1, %2;" : "=r"(h0) : "f"(v.y), "f"(v.x));
    asm("cvt.rn.bf16x2.f32 %0, %1, %2;" : "=r"(h1) : "f"(v.w), "f"(v.z));
    float rx = v.x - __uint_as_float(h0 << 16);
    float ry = v.y - __uint_as_float(h0 & 0xffff0000u);
    float rz = v.z - __uint_as_float(h1 << 16);
    float rw = v.w - __uint_as_float(h1 & 0xffff0000u);
    asm("cvt.rn.bf16x2.f32 %0, %1, %2;" : "=r"(q0) : "f"(ry), "f"(rx));
    asm("cvt.rn.bf16x2.f32 %0, %1, %2;" : "=r"(q1) : "f"(rw), "f"(rz));
}

__device__ __forceinline__ void cp_async16(uint32_t dst, const void* src) {
    asm volatile("cp.async.cg.shared.global [%0], [%1], 16;\n" :: "r"(dst), "l"(src));
}
__device__ __forceinline__ void cp_commit() {
    asm volatile("cp.async.commit_group;\n" ::: "memory");
}
template<int N> __device__ __forceinline__ void cp_wait() {
    asm volatile("cp.async.wait_group %0;\n" :: "n"(N) : "memory");
}

__global__ __launch_bounds__(THREADS, 5)
void linheads_mma_kernel(const float* __restrict__ x,
                         const float* __restrict__ v_conf,
                         const float* __restrict__ bias,
                         float* __restrict__ result,
                         float* __restrict__ out)
{
    // per-warp private ring: [warp][stage][buf][lane] x 16B = 32 KB
    __shared__ __align__(16) float4 xs[4][STAGES][4][32];

    const int t   = threadIdx.x;
    const int wid = t >> 5;
    const int l   = t & 31;

    const long long wb = (long long)blockIdx.x * BROWS + wid * WROWS;
    // frag rows (r, r+8) <-> global rows (2r, 2r+1); lane quad-row r = l>>2
    const float* p00 = x + (wb + 2 * (l >> 2)) * DIM + 4 * (l & 3);

    // this lane's 4 ring slots (one per buf) in each stage
    uint32_t ring0 = (uint32_t)__cvta_generic_to_shared(&xs[wid][0][0][l]);
    // stage stride = 4*32*16 = 2048 B; buf stride = 32*16 = 512 B

    float c[2][NT][4];
#pragma unroll
    for (int mt = 0; mt < 2; mt++)
#pragma unroll
        for (int nt = 0; nt < NT; nt++)
#pragma unroll
            for (int i = 0; i < 4; i++) c[mt][nt][i] = 0.f;

    // issue a stage: 4 x 16B cp.async for k-step ks into ring slot s
    auto issue = [&](int ks, int s) {
        const int o = ks * 16;
        uint32_t d = ring0 + (uint32_t)s * 2048;
        cp_async16(d,        p00 + o);
        cp_async16(d + 512,  p00 + DIM + o);
        cp_async16(d + 1024, p00 + 16 * DIM + o);
        cp_async16(d + 1536, p00 + 17 * DIM + o);
    };

    // prologue: stages 0..2 in flight (3 commit groups)
#pragma unroll
    for (int s = 0; s < STAGES - 1; s++) { issue(s, s); cp_commit(); }

#pragma unroll 4
    for (int ks = 0; ks < NKS; ks++) {
        const int s = ks & (STAGES - 1);

        // keep the pipe full: issue ks+3, always commit (empty group at tail)
        if (ks + STAGES - 1 < NKS) issue(ks + STAGES - 1, (ks + STAGES - 1) & (STAGES - 1));
        cp_commit();
        cp_wait<STAGES - 1>();           // stage ks resident (lane's own data)

        // read back this lane's 4 float4 and convert
        float4 b0 = xs[wid][s][0][l];
        float4 b1 = xs[wid][s][1][l];
        float4 b2 = xs[wid][s][2][l];
        float4 b3 = xs[wid][s][3][l];

        uint32_t ah[2][4], al[2][4];
        cvt4(b0, ah[0][0], ah[0][2], al[0][0], al[0][2]);
        cvt4(b1, ah[0][1], ah[0][3], al[0][1], al[0][3]);
        cvt4(b2, ah[1][0], ah[1][2], al[1][0], al[1][2]);
        cvt4(b3, ah[1][1], ah[1][3], al[1][1], al[1][3]);

#pragma unroll
        for (int nt = 0; nt < NT; nt++) {
            uint4 wf = g_wf[ks][nt][l];
#pragma unroll
            for (int mt = 0; mt < 2; mt++) {
                MMA(c[mt][nt], ah[mt][0], ah[mt][1], ah[mt][2], ah[mt][3], wf.x, wf.y);
                MMA(c[mt][nt], ah[mt][0], ah[mt][1], ah[mt][2], ah[mt][3], wf.z, wf.w);
                MMA(c[mt][nt], al[mt][0], al[mt][1], al[mt][2], al[mt][3], wf.x, wf.y);
            }
        }
    }

    // ---- epilogue ----
    // c[mt][nt][rr*2+e]: row = wb + 16mt + 2(l>>2) + rr, col = nt*8 + 2(l&3) + e
#pragma unroll
    for (int mt = 0; mt < 2; mt++) {
#pragma unroll
        for (int rr = 0; rr < 2; rr++) {
            const long long row = wb + 16 * mt + 2 * (l >> 2) + rr;
            float res = 0.f;
#pragma unroll
            for (int nt = 0; nt < NT; nt++) {
                int col0 = nt * 8 + 2 * (l & 3);
#pragma unroll
                for (int e = 0; e < 2; e++) {
                    int col = col0 + e;
                    if (col < NH) {
                        float o = c[mt][nt][rr * 2 + e] + bias[col];
                        out[row * NH + col] = o;
                        res += o * v_conf[row * NH + col];
                    }
                }
            }
            res += __shfl_xor_sync(0xffffffffu, res, 1);
            res += __shfl_xor_sync(0xffffffffu, res, 2);
            if ((l & 3) == 0) result[row] = res;
        }
    }
}

extern "C" void kernel_launch(void* const* d_in, const int* in_sizes, int n_in,
                              void* d_out, int out_size)
{
    const float* x      = (const float*)d_in[0];   // [B, DIM]
    const float* v_conf = (const float*)d_in[1];   // [B, NH]
    const float* W      = (const float*)d_in[2];   // [NH, DIM]
    const float* bias   = (const float*)d_in[3];   // [NH]

    float* result = (float*)d_out;                 // [B]
    float* out    = (float*)d_out + B_TOTAL;       // [B, NH]

    prep_wfrag<<<(NKS * NT * 32 + 255) / 256, 256>>>(W);

    dim3 grid(B_TOTAL / BROWS);                    // 1024
    linheads_mma_kernel<<<grid, THREADS>>>(x, v_conf, bias, result, out);
}

// round 13
// speedup vs baseline: 1.1434x; 1.0962x over previous
#include <cuda_runtime.h>
#include <cuda_bf16.h>
#include <cstdint>

#define B_TOTAL  131072
#define DIM      1024
#define NH       21
#define THREADS  128
#define WROWS    16                  // rows per warp (1 m16 tile)
#define BROWS    64                  // rows per block (4 warps)
#define NKS      (DIM / 16)          // 64 k16 steps
#define NT       3                   // n-tiles of 8 (21 -> 24)

// W fragments, k-permuted to match float4 lane loads.
// uint4 = {b0_hi, b1_hi, b0_lo, b1_lo}
__device__ uint4 g_wf[NKS][NT][32];

__global__ void prep_wfrag(const float* __restrict__ W)
{
    int idx = blockIdx.x * blockDim.x + threadIdx.x;
    if (idx >= NKS * NT * 32) return;
    int l  = idx & 31;
    int nt = (idx >> 5) % NT;
    int ks = idx / (NT * 32);
    int n  = nt * 8 + (l >> 2);
    int col = ks * 16 + 4 * (l & 3);
    float4 wv = make_float4(0.f, 0.f, 0.f, 0.f);
    if (n < NH) wv = *(const float4*)&W[(long long)n * DIM + col];
    uint32_t h0, h1, q0, q1;
    asm("cvt.rn.bf16x2.f32 %0, %1, %2;" : "=r"(h0) : "f"(wv.y), "f"(wv.x));
    asm("cvt.rn.bf16x2.f32 %0, %1, %2;" : "=r"(h1) : "f"(wv.w), "f"(wv.z));
    float rx = wv.x - __uint_as_float(h0 << 16);
    float ry = wv.y - __uint_as_float(h0 & 0xffff0000u);
    float rz = wv.z - __uint_as_float(h1 << 16);
    float rw = wv.w - __uint_as_float(h1 & 0xffff0000u);
    asm("cvt.rn.bf16x2.f32 %0, %1, %2;" : "=r"(q0) : "f"(ry), "f"(rx));
    asm("cvt.rn.bf16x2.f32 %0, %1, %2;" : "=r"(q1) : "f"(rw), "f"(rz));
    g_wf[ks][nt][l] = make_uint4(h0, h1, q0, q1);
}

#define MMA(c, a0, a1, a2, a3, b0, b1)                                          \
    asm("mma.sync.aligned.m16n8k16.row.col.f32.bf16.bf16.f32 "                  \
        "{%0,%1,%2,%3}, {%4,%5,%6,%7}, {%8,%9}, {%0,%1,%2,%3};"                 \
        : "+f"(c[0]), "+f"(c[1]), "+f"(c[2]), "+f"(c[3])                        \
        : "r"(a0), "r"(a1), "r"(a2), "r"(a3), "r"(b0), "r"(b1))

// float4 (4 consecutive k) -> two packed bf16x2 hi + two residual lo
__device__ __forceinline__ void cvt4(float4 v, uint32_t& h0, uint32_t& h1,
                                     uint32_t& q0, uint32_t& q1)
{
    asm("cvt.rn.bf16x2.f32 %0, %1, %2;" : "=r"(h0) : "f"(v.y), "f"(v.x));
    asm("cvt.rn.bf16x2.f32 %0, %1, %2;" : "=r"(h1) : "f"(v.w), "f"(v.z));
    float rx = v.x - __uint_as_float(h0 << 16);
    float ry = v.y - __uint_as_float(h0 & 0xffff0000u);
    float rz = v.z - __uint_as_float(h1 << 16);
    float rw = v.w - __uint_as_float(h1 & 0xffff0000u);
    asm("cvt.rn.bf16x2.f32 %0, %1, %2;" : "=r"(q0) : "f"(ry), "f"(rx));
    asm("cvt.rn.bf16x2.f32 %0, %1, %2;" : "=r"(q1) : "f"(rw), "f"(rz));
}

__global__ __launch_bounds__(THREADS, 6)
void linheads_mma_kernel(const float* __restrict__ x,
                         const float* __restrict__ v_conf,
                         const float* __restrict__ bias,
                         float* __restrict__ result,
                         float* __restrict__ out)
{
    const int t   = threadIdx.x;
    const int wid = t >> 5;
    const int l   = t & 31;

    const long long wb = (long long)blockIdx.x * BROWS + wid * WROWS;
    // frag rows (r, r+8) <-> global rows (2r, 2r+1); lane quad-row r = l>>2
    const float* p00 = x + (wb + 2 * (l >> 2)) * DIM + 4 * (l & 3);

    float c[NT][4];
#pragma unroll
    for (int nt = 0; nt < NT; nt++)
#pragma unroll
        for (int i = 0; i < 4; i++) c[nt][i] = 0.f;

    // cur[rr]: float4 at (row wb + 2(l>>2) + rr, k 16ks + 4(l&3))
    float4 cur[2];
    cur[0] = __ldcs((const float4*)(p00));
    cur[1] = __ldcs((const float4*)(p00 + DIM));

#pragma unroll 4
    for (int ks = 0; ks < NKS; ks++) {
        float4 nxt[2];
        if (ks + 1 < NKS) {
            const int o = (ks + 1) * 16;
            nxt[0] = __ldcs((const float4*)(p00 + o));
            nxt[1] = __ldcs((const float4*)(p00 + DIM + o));
        }

        // a0 = hi(row rr0, k 4q..4q+1), a1 = row rr1, a2/a3 = k 4q+2..3
        uint32_t ah[4], al[4];
        cvt4(cur[0], ah[0], ah[2], al[0], al[2]);
        cvt4(cur[1], ah[1], ah[3], al[1], al[3]);

#pragma unroll
        for (int nt = 0; nt < NT; nt++) {
            uint4 wf = g_wf[ks][nt][l];
            MMA(c[nt], ah[0], ah[1], ah[2], ah[3], wf.x, wf.y);
            MMA(c[nt], ah[0], ah[1], ah[2], ah[3], wf.z, wf.w);
            MMA(c[nt], al[0], al[1], al[2], al[3], wf.x, wf.y);
        }

        cur[0] = nxt[0];
        cur[1] = nxt[1];
    }

    // ---- epilogue ----
    // c[nt][rr*2+e]: row = wb + 2(l>>2) + rr, col = nt*8 + 2(l&3) + e
#pragma unroll
    for (int rr = 0; rr < 2; rr++) {
        const long long row = wb + 2 * (l >> 2) + rr;
        float res = 0.f;
#pragma unroll
        for (int nt = 0; nt < NT; nt++) {
            int col0 = nt * 8 + 2 * (l & 3);
#pragma unroll
            for (int e = 0; e < 2; e++) {
                int col = col0 + e;
                if (col < NH) {
                    float o = c[nt][rr * 2 + e] + bias[col];
                    out[row * NH + col] = o;
                    res += o * v_conf[row * NH + col];
                }
            }
        }
        res += __shfl_xor_sync(0xffffffffu, res, 1);
        res += __shfl_xor_sync(0xffffffffu, res, 2);
        if ((l & 3) == 0) result[row] = res;
    }
}

extern "C" void kernel_launch(void* const* d_in, const int* in_sizes, int n_in,
                              void* d_out, int out_size)
{
    const float* x      = (const float*)d_in[0];   // [B, DIM]
    const float* v_conf = (const float*)d_in[1];   // [B, NH]
    const float* W      = (const float*)d_in[2];   // [NH, DIM]
    const float* bias   = (const float*)d_in[3];   // [NH]

    float* result = (float*)d_out;                 // [B]
    float* out    = (float*)d_out + B_TOTAL;       // [B, NH]

    prep_wfrag<<<(NKS * NT * 32 + 255) / 256, 256>>>(W);

    dim3 grid(B_TOTAL / BROWS);                    // 2048
    linheads_mma_kernel<<<grid, THREADS>>>(x, v_conf, bias, result, out);
}